// round 15
// baseline (speedup 1.0000x reference)
#include <cuda_runtime.h>
#include <math.h>
#include <cstdint>

// ---------------- problem constants ----------------
#define BB      16
#define NN      128
#define RR      16256
#define OBJD    64
#define RELD    32
#define EFFD    100
#define RHID    150
#define RIN     160      // 2*OBJD + RELD
#define OIN     164      // OBJD + EFFD
#define OHID    100

#define TILE_R  128
#define NTILES  127      // RR / TILE_R
#define KSPLIT  9
#define THREADS 512      // 16 warps -> 4 warps/SMSP

// smem strides (floats), conflict-free for the PTX m16n8k8.tf32 fragment patterns:
//  A-operand (scalar ld at row*S + c, +4): S % 32 in {4,12,20,28}
//  B-operand scalar (c*S + g): S % 32 in {8,24}
//  B-operand PAIRED 64-bit ((c*S2) + 2*(n8+g)): S2 % 32 == 8 -> per-phase banks 8c+2g distinct
#define XS      164      // activations (A), 164%32=4
#define OTS     132      // O^T (A, gather), 132%32=4
#define SRS     132      // rel tile (A, scatter), 132%32=4
#define RTS     136      // rel tile (B, gather, scalar), 136%32=8
#define WST2    328      // weight stage interleaved (hi,lo) pairs, 328%32=8, covers 164 pairs
#define EST2    232      // effects stage interleaved pairs, 232%32=8, covers 116 pairs

#define KPADW   160      // all MLP layers padded to K=160 (10 chunks of 16)
#define WCHUNKS 10
#define CF2     (16 * WST2)     // floats per interleaved chunk = 5248
#define WOFF2   (KPADW * WST2)  // per-layer padded interleaved floats = 52480

// scratch (device globals: allocation-free per harness rules)
__device__ float g_effects[BB * RR * EFFD];                 // ~104 MB
__device__ float g_part[KSPLIT * BB * NN * EFFD];           // ~7.4 MB
__device__ float g_wi[4 * WOFF2];                           // pre-split weights, (hi,lo) interleaved

// ---------------- tf32 split helpers ----------------
__device__ __forceinline__ void split_tf32(float x, uint32_t& h, uint32_t& l) {
    asm("cvt.rna.tf32.f32 %0, %1;" : "=r"(h) : "f"(x));
    float r = x - __uint_as_float(h);      // exact
    asm("cvt.rna.tf32.f32 %0, %1;" : "=r"(l) : "f"(r));
}

// D += A(16x8,row) * B(8x8,col)  (tf32 inputs, f32 accum)
// PTX layout: a0=(g,c) a1=(g+8,c) a2=(g,c+4) a3=(g+8,c+4); b0=(c,g) b1=(c+4,g)
// C: c0=(g,2c) c1=(g,2c+1) c2=(g+8,2c) c3=(g+8,2c+1)
__device__ __forceinline__ void mma_tf32(float acc[4], const uint32_t a[4],
                                         uint32_t b0, uint32_t b1) {
    asm volatile(
        "mma.sync.aligned.m16n8k8.row.col.f32.tf32.tf32.f32 "
        "{%0,%1,%2,%3}, {%4,%5,%6,%7}, {%8,%9}, {%0,%1,%2,%3};\n"
        : "+f"(acc[0]), "+f"(acc[1]), "+f"(acc[2]), "+f"(acc[3])
        : "r"(a[0]), "r"(a[1]), "r"(a[2]), "r"(a[3]), "r"(b0), "r"(b1));
}

// load + split the A fragment: rows {row,row+8}, k-cols {kbase+c, kbase+c+4}
__device__ __forceinline__ void load_a_frag(const float* A, int row, int stride,
                                            int kbase, int c,
                                            uint32_t ah[4], uint32_t al[4]) {
    const float* Ap = A + row * stride + kbase + c;
    float x0 = Ap[0];
    float x1 = Ap[8 * stride];
    float x2 = Ap[4];
    float x3 = Ap[8 * stride + 4];
    split_tf32(x0, ah[0], al[0]);
    split_tf32(x1, ah[1], al[1]);
    split_tf32(x2, ah[2], al[2]);
    split_tf32(x3, ah[3], al[3]);
}

// ---------------- cp.async helpers ----------------
__device__ __forceinline__ void cpasync16(float* dst, const float* src) {
    unsigned d = (unsigned)__cvta_generic_to_shared(dst);
    asm volatile("cp.async.cg.shared.global [%0], [%1], 16;\n" :: "r"(d), "l"(src));
}
__device__ __forceinline__ void cpasync_commit() {
    asm volatile("cp.async.commit_group;\n" ::: "memory");
}
template<int N>
__device__ __forceinline__ void cpasync_wait() {
    asm volatile("cp.async.wait_group %0;\n" :: "n"(N) : "memory");
}

// ---------------- setup: pre-split all MLP weights, (hi,lo) interleaved ----------------
__global__ void split_weights_kernel(const float* __restrict__ rw1,
                                     const float* __restrict__ rw2,
                                     const float* __restrict__ rw3,
                                     const float* __restrict__ rw4)
{
    int i = blockIdx.x * blockDim.x + threadIdx.x;
    if (i >= 4 * KPADW * 152) return;
    int layer = i / (KPADW * 152), rem = i - layer * (KPADW * 152);
    int k = rem / 152, cc = rem - k * 152;
    const float* W; int K, NOUT;
    switch (layer) {
        case 0:  W = rw1; K = RIN;  NOUT = RHID; break;
        case 1:  W = rw2; K = RHID; NOUT = RHID; break;
        case 2:  W = rw3; K = RHID; NOUT = RHID; break;
        default: W = rw4; K = RHID; NOUT = EFFD; break;
    }
    float v = (k < K && cc < NOUT) ? W[k * NOUT + cc] : 0.f;
    uint32_t h, l;
    split_tf32(v, h, l);
    float* dst = g_wi + (size_t)layer * WOFF2 + k * WST2 + cc * 2;
    dst[0] = __uint_as_float(h);
    dst[1] = __uint_as_float(l);
}

// ---------------- fused relation-MLP layer (3xTF32, interleaved 2-stage weights) ----------------
// A: smem [128, XS] raw fp32 (cols [0,160) valid). Weights: g_wi + layer*WOFF2.
// wbuf: 2 stages x CF2.
template<int NOUT, bool TO_GLOBAL>
__device__ __forceinline__ void mlp_layer_mma(
    const float* A, int layer, const float* __restrict__ bias,
    float* Cs, float* Cg, float* wbuf, int tid)
{
    constexpr int NT  = (NOUT + 7) / 8;
    constexpr int NTW = (NT + 3) / 4;
    const int lane = tid & 31, warp = tid >> 5;
    const int g = lane >> 2, c = lane & 3;
    const int mwarp = warp & 3, nwarp = warp >> 2;
    const int mrow  = mwarp * 32 + g;
    const int nbase = nwarp * NTW;

    const float* Wi = g_wi + (size_t)layer * WOFF2;

    float acc[2][NTW][4];
#pragma unroll
    for (int mt = 0; mt < 2; mt++)
#pragma unroll
        for (int j = 0; j < NTW; j++)
#pragma unroll
            for (int q = 0; q < 4; q++) acc[mt][j][q] = 0.f;

    auto issue_copy = [&](int chunk, int stage) {
        float* sh = wbuf + stage * CF2;
        const float* gw = Wi + chunk * CF2;
        for (int idx = tid; idx < CF2 / 4; idx += THREADS)
            cpasync16(sh + idx * 4, gw + idx * 4);
    };

    issue_copy(0, 0); cpasync_commit();

    for (int i = 0; i < WCHUNKS; i++) {
        cpasync_wait<0>();       // chunk i landed
        __syncthreads();         // visible to all; prior compute done (stage (i+1)&1 free)
        if (i + 1 < WCHUNKS) issue_copy(i + 1, (i + 1) & 1);
        cpasync_commit();        // always (group alignment)

        const float* sW = wbuf + (i & 1) * CF2;
        const int k0 = i * 16;

        // hoist ALL A fragments for this chunk (2 ks-rounds x 2 m-tiles)
        uint32_t ah[2][2][4], al[2][2][4];
#pragma unroll
        for (int ks2 = 0; ks2 < 2; ks2++)
#pragma unroll
            for (int mt = 0; mt < 2; mt++)
                load_a_frag(A, mrow + mt * 16, XS, k0 + ks2 * 8, c,
                            ah[ks2][mt], al[ks2][mt]);

#pragma unroll
        for (int ks2 = 0; ks2 < 2; ks2++) {
            const int base = (ks2 * 8 + c) * WST2;
#pragma unroll
            for (int j = 0; j < NTW; j++) {
                int nt = nbase + j;
                if (nt < NT) {
                    float2 p0 = *((const float2*)(sW + base) + nt * 8 + g);
                    float2 p1 = *((const float2*)(sW + base + 4 * WST2) + nt * 8 + g);
                    uint32_t bh0 = __float_as_uint(p0.x), bl0 = __float_as_uint(p0.y);
                    uint32_t bh1 = __float_as_uint(p1.x), bl1 = __float_as_uint(p1.y);
#pragma unroll
                    for (int mt = 0; mt < 2; mt++) {
                        mma_tf32(acc[mt][j], al[ks2][mt], bh0, bh1);
                        mma_tf32(acc[mt][j], ah[ks2][mt], bl0, bl1);
                        mma_tf32(acc[mt][j], ah[ks2][mt], bh0, bh1);
                    }
                }
            }
        }
    }

    // epilogue: c0 (r,2c) c1 (r,2c+1) c2 (r+8,2c) c3 (r+8,2c+1)
#pragma unroll
    for (int mt = 0; mt < 2; mt++)
#pragma unroll
        for (int j = 0; j < NTW; j++) {
            int nt = nbase + j;
            if (nt < NT) {
#pragma unroll
                for (int q = 0; q < 4; q++) {
                    int col = nt * 8 + 2 * c + (q & 1);
                    int r   = mwarp * 32 + mt * 16 + g + ((q & 2) ? 8 : 0);
                    if (TO_GLOBAL) {
                        if (col < NOUT)
                            Cg[r * NOUT + col] = fmaxf(acc[mt][j][q] + __ldg(&bias[col]), 0.f);
                    } else {
                        float o = (col < NOUT) ? fmaxf(acc[mt][j][q] + __ldg(&bias[col]), 0.f) : 0.f;
                        Cs[r * XS + col] = o;
                    }
                }
            }
        }
    if (!TO_GLOBAL && NT * 8 < KPADW) {
        // zero-pad cols [NT*8, 160) so next layer's padded-K reads are exact zeros
        constexpr int PADW = KPADW - NT * 8;
        for (int idx = tid; idx < NN * PADW; idx += THREADS) {
            int r = idx / PADW, cc = idx - r * PADW;
            Cs[r * XS + NT * 8 + cc] = 0.f;
        }
    }
    __syncthreads();   // Cs visible to next layer; wbuf reads drained
}

// ---------------- kernel A: gather + 4-layer relation MLP ----------------
// grid (NTILES, BB), 512 threads
__global__ __launch_bounds__(THREADS, 1)
void gather_mlp_kernel(const float* __restrict__ objects,
                       const float* __restrict__ srel,
                       const float* __restrict__ rrel,
                       const float* __restrict__ relinfo,
                       const float* __restrict__ rb1, const float* __restrict__ rb2,
                       const float* __restrict__ rb3, const float* __restrict__ rb4)
{
    extern __shared__ float smem[];
    float* bufX = smem;                    // 128 x XS raw fp32
    float* bufH = bufX + NN * XS;          // 128 x XS; during gather: rel tile [128 x RTS]
    float* wbuf = bufH + NN * XS;          // 2*CF2 = 10496 floats; gather: O^T [64 x OTS = 8448]

    const int tid  = threadIdx.x;
    const int lane = tid & 31, warp = tid >> 5;
    const int g = lane >> 2, c = lane & 3;
    const int t = blockIdx.x, b = blockIdx.y;
    const int r0 = t * TILE_R;

    // issue pass-0 rel tile copy FIRST (overlaps with O^T / relinfo staging)
    {
        const float* Rel = srel;
        for (int idx = tid; idx < NN * 32; idx += THREADS) {
            int n = idx >> 5, w = idx & 31;
            cpasync16(bufH + n * RTS + w * 4,
                      Rel + ((size_t)b * NN + n) * RR + r0 + w * 4);
        }
        cpasync_commit();
    }

    // stage O^T (raw fp32): wbuf[d*OTS + n] = O[n][d]
    const float* Ob = objects + (size_t)b * NN * OBJD;
    for (int i = tid; i < NN * OBJD; i += THREADS) {
        int n = i >> 6, d = i & 63;
        wbuf[d * OTS + n] = Ob[i];
    }

    // relation_info -> bufX[:, 128:160]
    const float* RI = relinfo + ((size_t)b * RR + r0) * RELD;
    for (int i = tid; i < TILE_R * RELD; i += THREADS) {
        int r = i >> 5, cc = i & 31;
        bufX[r * XS + 128 + cc] = RI[i];
    }

    // gather via mma: D[d][r] = sum_n O^T[d][n] * Rel[n][r]
    // 16 warps: mw = d-tile (4 x m16 = 64 rows), rh = r-quarter (4 x 4 n8 tiles)
    const int mw = warp & 3;
    const int rh = warp >> 2;
    for (int pass = 0; pass < 2; ++pass) {
        cpasync_wait<0>();
        __syncthreads();       // rel tile + (pass0: O^T, relinfo) staged for all

        float acc[4][4];
#pragma unroll
        for (int nt = 0; nt < 4; nt++)
#pragma unroll
            for (int q = 0; q < 4; q++) acc[nt][q] = 0.f;

        for (int ks = 0; ks < NN; ks += 8) {
            uint32_t ah[4], al[4];
            load_a_frag(wbuf, mw * 16 + g, OTS, ks, c, ah, al);
            const float* Bp = bufH + (ks + c) * RTS + rh * 32 + g;
#pragma unroll
            for (int nt = 0; nt < 4; nt++) {
                uint32_t bh0, bl0, bh1, bl1;
                split_tf32(Bp[nt * 8], bh0, bl0);
                split_tf32(Bp[4 * RTS + nt * 8], bh1, bl1);
                mma_tf32(acc[nt], al, bh0, bh1);
                mma_tf32(acc[nt], ah, bl0, bl1);
                mma_tf32(acc[nt], ah, bh0, bh1);
            }
        }
        // D[d][r] -> bufX[r*XS + pass*64 + d]
#pragma unroll
        for (int nt = 0; nt < 4; nt++) {
#pragma unroll
            for (int q = 0; q < 4; q++) {
                int d = mw * 16 + g + ((q & 2) ? 8 : 0);
                int r = rh * 32 + nt * 8 + 2 * c + (q & 1);
                bufX[r * XS + pass * 64 + d] = acc[nt][q];
            }
        }
        if (pass == 0) {
            __syncthreads();   // all warps done reading bufH (pass-0 tile)
            for (int idx = tid; idx < NN * 32; idx += THREADS) {
                int n = idx >> 5, w = idx & 31;
                cpasync16(bufH + n * RTS + w * 4,
                          rrel + ((size_t)b * NN + n) * RR + r0 + w * 4);
            }
            cpasync_commit();
        }
    }
    __syncthreads();   // gather done; wbuf (O^T) + bufH free

    float* effp = g_effects + ((size_t)b * RR + r0) * EFFD;

    mlp_layer_mma<RHID, false>(bufX, 0, rb1, bufH, nullptr, wbuf, tid);
    mlp_layer_mma<RHID, false>(bufH, 1, rb2, bufX, nullptr, wbuf, tid);
    mlp_layer_mma<RHID, false>(bufX, 2, rb3, bufH, nullptr, wbuf, tid);
    mlp_layer_mma<EFFD, true >(bufH, 3, rb4, nullptr, effp, wbuf, tid);
}

// ---------------- kernel B: scatter (split-K, 3xTF32, interleaved effects) ----------------
// grid (KSPLIT, BB), 512 threads.  D[n][e] = sum_r Rel[n][r] * E[r][e]
__global__ __launch_bounds__(THREADS, 1)
void scatter_kernel(const float* __restrict__ rrel)
{
    extern __shared__ float smem[];
    float* sR = smem;                  // 128 x SRS raw fp32 (A operand)
    float* sE = sR + NN * SRS;         // 128 x EST2 interleaved (hi,lo) pairs (B operand)
    const int tid  = threadIdx.x;
    const int lane = tid & 31, warp = tid >> 5;
    const int g = lane >> 2, c = lane & 3;
    const int mwarp = warp & 3, nwarp = warp >> 2;
    const int mrow  = mwarp * 32 + g;
    const int split = blockIdx.x, b = blockIdx.y;

    constexpr int NT = (EFFD + 7) / 8;   // 13
    constexpr int NTW = (NT + 3) / 4;    // 4
    const int nbase = nwarp * NTW;

    float acc[2][NTW][4];
#pragma unroll
    for (int mt = 0; mt < 2; mt++)
#pragma unroll
        for (int j = 0; j < NTW; j++)
#pragma unroll
            for (int q = 0; q < 4; q++) acc[mt][j][q] = 0.f;

    for (int t = split; t < NTILES; t += KSPLIT) {
        int r0 = t * TILE_R;
        __syncthreads();    // prior tile's compute done before restaging
        // rel tile via cp.async (overlaps with effects staging below)
        for (int idx = tid; idx < NN * 32; idx += THREADS) {
            int n = idx >> 5, w = idx & 31;
            cpasync16(sR + n * SRS + w * 4,
                      rrel + ((size_t)b * NN + n) * RR + r0 + w * 4);
        }
        cpasync_commit();
        // effects tile: LDG + split + paired STS.64 (pairs e in [0,104), pad zeroed)
        const float* E = g_effects + ((size_t)b * RR + r0) * EFFD;
        for (int i = tid; i < TILE_R * 104; i += THREADS) {
            int r = i / 104, e = i - r * 104;
            float v = (e < EFFD) ? E[r * EFFD + e] : 0.f;
            uint32_t h, l;
            split_tf32(v, h, l);
            float2 p; p.x = __uint_as_float(h); p.y = __uint_as_float(l);
            *((float2*)(sE + r * EST2) + e) = p;
        }
        cpasync_wait<0>();
        __syncthreads();
        for (int ks = 0; ks < TILE_R; ks += 8) {
            uint32_t ah[2][4], al[2][4];
#pragma unroll
            for (int mt = 0; mt < 2; mt++)
                load_a_frag(sR, mrow + mt * 16, SRS, ks, c, ah[mt], al[mt]);
            const int base = (ks + c) * EST2;
#pragma unroll
            for (int j = 0; j < NTW; j++) {
                int nt = nbase + j;
                if (nt < NT) {
                    float2 p0 = *((const float2*)(sE + base) + nt * 8 + g);
                    float2 p1 = *((const float2*)(sE + base + 4 * EST2) + nt * 8 + g);
                    uint32_t bh0 = __float_as_uint(p0.x), bl0 = __float_as_uint(p0.y);
                    uint32_t bh1 = __float_as_uint(p1.x), bl1 = __float_as_uint(p1.y);
#pragma unroll
                    for (int mt = 0; mt < 2; mt++) {
                        mma_tf32(acc[mt][j], al[mt], bh0, bh1);
                        mma_tf32(acc[mt][j], ah[mt], bl0, bl1);
                        mma_tf32(acc[mt][j], ah[mt], bh0, bh1);
                    }
                }
            }
        }
    }

    float* P = g_part + ((size_t)split * BB + b) * NN * EFFD;
#pragma unroll
    for (int mt = 0; mt < 2; mt++)
#pragma unroll
        for (int j = 0; j < NTW; j++) {
            int nt = nbase + j;
            if (nt < NT) {
#pragma unroll
                for (int q = 0; q < 4; q++) {
                    int e = nt * 8 + 2 * c + (q & 1);
                    int n = mwarp * 32 + mt * 16 + g + ((q & 2) ? 8 : 0);
                    if (e < EFFD) P[n * EFFD + e] = acc[mt][j][q];
                }
            }
        }
}

// ---------------- kernel D: fused reduce + final object MLP + sigmoid ----------------
__global__ __launch_bounds__(128)
void final_kernel(const float* __restrict__ objects,
                  const float* __restrict__ ow1, const float* __restrict__ ob1,
                  const float* __restrict__ ow2, const float* __restrict__ ob2,
                  float* __restrict__ out)
{
    __shared__ float y[OIN];
    __shared__ float red[128];
    const int row = blockIdx.x;
    const int t = threadIdx.x;

    if (t < OBJD) y[t] = objects[(size_t)row * OBJD + t];
    if (t < EFFD) {
        float s = 0.f;
#pragma unroll
        for (int k = 0; k < KSPLIT; ++k)
            s += g_part[(size_t)k * (BB * NN * EFFD) + (size_t)row * EFFD + t];
        y[OBJD + t] = s;
    }
    __syncthreads();

    float v = 0.f;
    if (t < OHID) {
        float acc = ob1[t];
#pragma unroll 4
        for (int k = 0; k < OIN; ++k) acc = fmaf(y[k], ow1[k * OHID + t], acc);
        v = fmaxf(acc, 0.f) * ow2[t];
    }
    red[t] = v;
    __syncthreads();
    for (int s = 64; s > 0; s >>= 1) {
        if (t < s) red[t] += red[t + s];
        __syncthreads();
    }
    if (t == 0) out[row] = 1.f / (1.f + expf(-(red[0] + ob2[0])));
}

// ---------------- launch ----------------
extern "C" void kernel_launch(void* const* d_in, const int* in_sizes, int n_in,
                              void* d_out, int out_size)
{
    const float* objects = (const float*)d_in[0];
    const float* srel    = (const float*)d_in[1];
    const float* rrel    = (const float*)d_in[2];
    const float* relinfo = (const float*)d_in[3];
    const float* rw1 = (const float*)d_in[4];
    const float* rb1 = (const float*)d_in[5];
    const float* rw2 = (const float*)d_in[6];
    const float* rb2 = (const float*)d_in[7];
    const float* rw3 = (const float*)d_in[8];
    const float* rb3 = (const float*)d_in[9];
    const float* rw4 = (const float*)d_in[10];
    const float* rb4 = (const float*)d_in[11];
    const float* ow1 = (const float*)d_in[12];
    const float* ob1 = (const float*)d_in[13];
    const float* ow2 = (const float*)d_in[14];
    const float* ob2 = (const float*)d_in[15];
    float* out = (float*)d_out;

    // gather smem: 2 activation buffers + 2-stage interleaved weight pipeline
    const int AUX_FLOATS   = 2 * CF2;                                         // 10496 (>= 64*OTS=8448)
    const int GATHER_SMEM  = (2 * NN * XS + AUX_FLOATS) * (int)sizeof(float); // 209920 B
    const int SCATTER_SMEM = (NN * SRS + NN * EST2) * (int)sizeof(float);     // 186368 B

    cudaFuncSetAttribute(gather_mlp_kernel, cudaFuncAttributeMaxDynamicSharedMemorySize, GATHER_SMEM);
    cudaFuncSetAttribute(scatter_kernel,   cudaFuncAttributeMaxDynamicSharedMemorySize, SCATTER_SMEM);

    split_weights_kernel<<<(4 * KPADW * 152 + 255) / 256, 256>>>(rw1, rw2, rw3, rw4);

    gather_mlp_kernel<<<dim3(NTILES, BB), THREADS, GATHER_SMEM>>>(
        objects, srel, rrel, relinfo, rb1, rb2, rb3, rb4);

    scatter_kernel<<<dim3(KSPLIT, BB), THREADS, SCATTER_SMEM>>>(rrel);

    final_kernel<<<BB * NN, 128>>>(objects, ow1, ob1, ow2, ob2, out);
}